// round 8
// baseline (speedup 1.0000x reference)
#include <cuda_runtime.h>
#include <cstdint>

// ---------------------------------------------------------------------------
// RnnModelInterp v5: persistent kernel, 128 CTAs x 256 thr, tf32 tensor cores.
//   v4b + (1) double-buffered staging: ONE __syncthreads per chunk
//        (2) even/odd-k split MMA accumulators (dependent-HMMA chain 4->2)
//        (3) phase-C float4 accumulators (FFMA chain 64->16 per chunk)
//        (4) Wm head slice moved to global scratch (funds the double buffer)
// ---------------------------------------------------------------------------

#define GRIDN    128
#define NTHREADS 256

#define T_STEPS 199
#define BATCH   256
#define H       512
#define NC      3
#define NM      64

#define NCH_A   10
#define NCH_B   16
#define SPLIT_A 2
#define SPLIT_B 8
#define START_A 2
#define START_B 8

#define SA      644            // W0t row stride
#define SB      1028           // W1t row stride
#define SH      68             // staging row stride (mod 32 == 4: conflict-free frags)
#define SE      34             // epilogue scratch row stride (even)
#define BUFSZ   (32 * SH)      // one staging buffer

#define OFF_W0  0
#define OFF_W1  (OFF_W0 + 32 * SA)             // 20608
#define OFF_HS  (OFF_W1 + 32 * SB)             // 53504 (double buffer: 2*2176)
#define OFF_B0  (OFF_HS + 2 * BUFSZ)           // 57856
#define OFF_B1  (OFF_B0 + 32)
#define OFF_LG  (OFF_B1 + 32)
#define SMEM_FLOATS (OFF_LG + 96)              // 58016
#define SMEM_BYTES  (SMEM_FLOATS * 4)          // 232064 <= 232448

typedef unsigned long long ull;

__device__ float g_h0[2][BATCH * H];
__device__ float g_h1[2][BATCH * H];
__device__ float g_Xp[BATCH * 128];
__device__ float g_Wct[NC * H];
__device__ float g_Wmt[NM * H];            // transposed Wm: [c*H + k]
__device__ ull   g_barcnt;

__device__ __forceinline__ uint32_t tf32r(float f) {
    uint32_t u;
    asm("cvt.rna.tf32.f32 %0, %1;" : "=r"(u) : "f"(f));
    return u;
}

__device__ __forceinline__ void mma8(float* c,
    uint32_t a0, uint32_t a1, uint32_t a2, uint32_t a3,
    uint32_t b0, uint32_t b1)
{
    asm volatile("mma.sync.aligned.m16n8k8.row.col.f32.tf32.tf32.f32 "
        "{%0,%1,%2,%3}, {%4,%5,%6,%7}, {%8,%9}, {%0,%1,%2,%3};"
        : "+f"(c[0]), "+f"(c[1]), "+f"(c[2]), "+f"(c[3])
        : "r"(a0), "r"(a1), "r"(a2), "r"(a3), "r"(b0), "r"(b1));
}

__device__ __forceinline__ void gridbar() {
    __syncthreads();
    if (threadIdx.x == 0) {
        ull old;
        asm volatile("atom.release.gpu.global.add.u64 %0, [%1], 1;"
                     : "=l"(old) : "l"(&g_barcnt) : "memory");
        ull target = old - (old & (ull)(GRIDN - 1)) + (ull)GRIDN;
        ull v;
        int polls = 0;
        for (;;) {
            asm volatile("ld.acquire.gpu.global.u64 %0, [%1];"
                         : "=l"(v) : "l"(&g_barcnt) : "memory");
            if (v >= target) break;
            if (++polls > 4096) __nanosleep(64);
        }
    }
    __syncthreads();
}

__device__ __forceinline__ void ld_chunk(
    const float* __restrict__ srcA, int strideA, int splitCh,
    const float* __restrict__ srcB, int strideB,
    int ch, int rbase, int srow, int sinner, float4& a, float4& b)
{
    const float* p;
    if (ch < splitCh) p = srcA + (size_t)(rbase + srow) * strideA + ch * 64 + sinner;
    else              p = srcB + (size_t)(rbase + srow) * strideB + (ch - splitCh) * 64 + sinner;
    a = *(const float4*)p;
    b = *(const float4*)(p + 4);
}

__device__ __forceinline__ void stage_store_tf32(float* sp, const float4& a, const float4& b) {
    sp[0] = __uint_as_float(tf32r(a.x));
    sp[1] = __uint_as_float(tf32r(a.y));
    sp[2] = __uint_as_float(tf32r(a.z));
    sp[3] = __uint_as_float(tf32r(a.w));
    sp[4] = __uint_as_float(tf32r(b.x));
    sp[5] = __uint_as_float(tf32r(b.y));
    sp[6] = __uint_as_float(tf32r(b.z));
    sp[7] = __uint_as_float(tf32r(b.w));
}

// tf32 GEMM phase: dst[32x32] = tanh(act @ Wt^T + b). One sync per chunk.
__device__ __forceinline__ void mm_phase(
    const float* __restrict__ srcA, int strideA, int splitCh,
    const float* __restrict__ srcB, int strideB, int nch, int start,
    float4 a0, float4 b0, float4 a1, float4 b1,
    const float* __restrict__ Wt, int wstride, const float* __restrict__ bs,
    float* __restrict__ hs, float* __restrict__ dst, int rbase, int colbase)
{
    const int tid = threadIdx.x;
    const int w = tid >> 5, lane = tid & 31;
    const int g = lane >> 2, tig = lane & 3;
    const int kh = w >> 2, wr = (w >> 1) & 1, wc = w & 1;
    const int srow = tid >> 3, sinner = (tid & 7) << 3;

    float accE[8], accO[8];
#pragma unroll
    for (int i = 0; i < 8; i++) { accE[i] = 0.f; accO[i] = 0.f; }

    const int ar0 = (wr * 16 + g) * SH;
    const int ar1 = (wr * 16 + g + 8) * SH;
    const float* wn0 = Wt + (wc * 16 + g) * wstride;
    const float* wn1 = Wt + (wc * 16 + 8 + g) * wstride;
    const int kk = kh * 32;

    // initial store: chunk `start` -> buf0
    stage_store_tf32(hs + srow * SH + sinner, a0, b0);
    __syncthreads();
    a0 = a1; b0 = b1;          // pipeline register: chunk start+1

    for (int i = 0; i < nch; i++) {
        int ch = start + i; if (ch >= nch) ch -= nch;
        float* cur = hs + (i & 1) * BUFSZ;
        // store chunk i+1 (in a0,b0) into the other buffer
        if (i + 1 < nch) {
            float* nxt = hs + ((i + 1) & 1) * BUFSZ;
            stage_store_tf32(nxt + srow * SH + sinner, a0, b0);
        }
        // preload chunk i+2
        if (i + 2 < nch) {
            int ch2 = start + i + 2; if (ch2 >= nch) ch2 -= nch;
            ld_chunk(srcA, strideA, splitCh, srcB, strideB, ch2, rbase, srow, sinner, a0, b0);
        }
        const float* wa = wn0 + ch * 64 + kk;
        const float* wb = wn1 + ch * 64 + kk;
#pragma unroll
        for (int ks = 0; ks < 4; ks++) {
            const int kx = kk + ks * 8;
            uint32_t A0 = __float_as_uint(cur[ar0 + kx + tig]);
            uint32_t A1 = __float_as_uint(cur[ar1 + kx + tig]);
            uint32_t A2 = __float_as_uint(cur[ar0 + kx + tig + 4]);
            uint32_t A3 = __float_as_uint(cur[ar1 + kx + tig + 4]);
            uint32_t B0 = __float_as_uint(wa[ks * 8 + tig]);
            uint32_t B1 = __float_as_uint(wa[ks * 8 + tig + 4]);
            uint32_t B2 = __float_as_uint(wb[ks * 8 + tig]);
            uint32_t B3 = __float_as_uint(wb[ks * 8 + tig + 4]);
            float* tA = (ks & 1) ? accO : accE;
            mma8(tA,     A0, A1, A2, A3, B0, B1);
            mma8(tA + 4, A0, A1, A2, A3, B2, B3);
        }
        __syncthreads();
    }

    float acc[8];
#pragma unroll
    for (int i = 0; i < 8; i++) acc[i] = accE[i] + accO[i];

    // K-half reduction via hs base (all staging reads done after final sync)
    if (kh == 1) {
#pragma unroll
        for (int nt = 0; nt < 2; nt++) {
            const int cl = wc * 16 + nt * 8 + 2 * tig;
            *(float2*)&hs[(wr*16 + g)     * SE + cl] = make_float2(acc[nt*4+0], acc[nt*4+1]);
            *(float2*)&hs[(wr*16 + g + 8) * SE + cl] = make_float2(acc[nt*4+2], acc[nt*4+3]);
        }
    }
    __syncthreads();
    if (kh == 0) {
#pragma unroll
        for (int nt = 0; nt < 2; nt++) {
            const int cl = wc * 16 + nt * 8 + 2 * tig;
            float2 p0 = *(float2*)&hs[(wr*16 + g)     * SE + cl];
            float2 p1 = *(float2*)&hs[(wr*16 + g + 8) * SE + cl];
            float o0 = tanhf(acc[nt*4+0] + p0.x + bs[cl]);
            float o1 = tanhf(acc[nt*4+1] + p0.y + bs[cl + 1]);
            float o2 = tanhf(acc[nt*4+2] + p1.x + bs[cl]);
            float o3 = tanhf(acc[nt*4+3] + p1.y + bs[cl + 1]);
            *(float2*)&dst[(size_t)(rbase + wr*16 + g)     * H + colbase + cl] = make_float2(o0, o1);
            *(float2*)&dst[(size_t)(rbase + wr*16 + g + 8) * H + colbase + cl] = make_float2(o2, o3);
        }
    }
}

// ---------------------------------------------------------------------------
__global__ void __launch_bounds__(NTHREADS, 1)
rnn_kernel(const float* __restrict__ cat_seq, const float* __restrict__ val_seq,
           const float* __restrict__ W_ih0, const float* __restrict__ W_hh0,
           const float* __restrict__ b0,
           const float* __restrict__ W_ih1, const float* __restrict__ W_hh1,
           const float* __restrict__ b1,
           const float* __restrict__ Wc, const float* __restrict__ bc,
           const float* __restrict__ Wm, const float* __restrict__ bm,
           float* __restrict__ out)
{
    extern __shared__ float sm[];
    float* W0s = sm + OFF_W0;
    float* W1s = sm + OFF_W1;
    float* hs  = sm + OFF_HS;
    float* bs0 = sm + OFF_B0;
    float* bs1 = sm + OFF_B1;
    float* slg = sm + OFF_LG;

    const int tid = threadIdx.x;
    const int cta = blockIdx.x;
    const int ri  = cta >> 4;
    const int cj  = cta & 15;
    const int rbase   = ri * 32;
    const int colbase = cj * 32;

    // ---- per-launch init ----
    {
        int gt = cta * NTHREADS + tid;
        for (int i = gt; i < BATCH * H; i += GRIDN * NTHREADS) {
            g_h0[0][i] = 0.f;
            g_h1[0][i] = 0.f;
        }
        for (int i = gt; i < BATCH * 128; i += GRIDN * NTHREADS) {
            int r = i >> 7, s = i & 127;
            float v = 0.f;
            if (s < NC)           v = cat_seq[r * NC + s];
            else if (s < NC + NM) v = val_seq[r * NM + (s - NC)];
            g_Xp[i] = v;
        }
        for (int i = gt; i < NC * H; i += GRIDN * NTHREADS) {
            int j = i >> 9, k = i & (H - 1);
            g_Wct[i] = Wc[k * NC + j];
        }
        for (int i = gt; i < NM * H; i += GRIDN * NTHREADS) {
            int c = i >> 9, k = i & (H - 1);
            g_Wmt[i] = Wm[k * NM + c];
        }
    }

    // ---- SMEM weight slices (transposed, tf32-rounded) ----
    for (int idx = tid; idx < 32 * SA; idx += NTHREADS) {
        int c = idx / SA, k = idx - c * SA;
        float v = 0.f;
        if (k < NC + NM)              v = W_ih0[k * H + colbase + c];
        else if (k >= 128 && k < 640) v = W_hh0[(k - 128) * H + colbase + c];
        W0s[idx] = __uint_as_float(tf32r(v));
    }
    for (int idx = tid; idx < 32 * SB; idx += NTHREADS) {
        int c = idx / SB, k = idx - c * SB;
        float v = 0.f;
        if (k < H)         v = W_ih1[k * H + colbase + c];
        else if (k < 2*H)  v = W_hh1[(k - H) * H + colbase + c];
        W1s[idx] = __uint_as_float(tf32r(v));
    }
    if (tid < 32) { bs0[tid] = b0[colbase + tid]; bs1[tid] = b1[colbase + tid]; }
    gridbar();

    const int vr = tid >> 2, vc = tid & 3;
    const int t2 = tid - 128;
    const int rl = (t2 >= 0) ? t2 / 3 : 0, jj = (t2 >= 0) ? t2 - rl * 3 : 0;
    const int srow = tid >> 3, sinner = (tid & 7) << 3;
    const float* wmp = g_Wmt + (size_t)((cj << 2) + vc) * H;   // val-head col
    const float* wcp = g_Wct + (size_t)jj * H;                 // logit col

    // preload phase-A chunks (START_A, START_A+1) for t=0
    float4 pAa0, pAb0, pAa1, pAb1;
    ld_chunk(g_Xp, 128, SPLIT_A, g_h0[0], H, START_A,     rbase, srow, sinner, pAa0, pAb0);
    ld_chunk(g_Xp, 128, SPLIT_A, g_h0[0], H, START_A + 1, rbase, srow, sinner, pAa1, pAb1);

    // ---- time loop ----
    for (int t = 0; t < T_STEPS; t++) {
        const int p = t & 1;
        const float* H0r = g_h0[p];   float* H0w = g_h0[p ^ 1];
        const float* H1r = g_h1[p];   float* H1w = g_h1[p ^ 1];

        // Phase A
        mm_phase(g_Xp, 128, SPLIT_A, H0r, H, NCH_A, START_A,
                 pAa0, pAb0, pAa1, pAb1, W0s, SA, bs0, hs, H0w, rbase, colbase);

        // preload phase-B chunks from H1r (stable) BEFORE barrier
        float4 pBa0, pBb0, pBa1, pBb1;
        ld_chunk(H0w, H, SPLIT_B, H1r, H, START_B,     rbase, srow, sinner, pBa0, pBb0);
        ld_chunk(H0w, H, SPLIT_B, H1r, H, START_B + 1, rbase, srow, sinner, pBa1, pBb1);
        gridbar();

        // Phase B
        mm_phase(H0w, H, SPLIT_B, H1r, H, NCH_B, START_B,
                 pBa0, pBb0, pBa1, pBb1, W1s, SB, bs1, hs, H1w, rbase, colbase);
        gridbar();

        // Phase C: heads (double-buffered staging, float4 accumulators)
        {
            float4 acc4 = make_float4(0.f, 0.f, 0.f, 0.f);
            float4 a0, b0;
            ld_chunk(H1w, H, 8, H1w, H, 0, rbase, srow, sinner, a0, b0);
            // initial store chunk0 (fp32, no rounding)
            *(float4*)(hs + srow * SH + sinner)     = a0;
            *(float4*)(hs + srow * SH + sinner + 4) = b0;
            ld_chunk(H1w, H, 8, H1w, H, 1, rbase, srow, sinner, a0, b0);
            __syncthreads();
            for (int ch = 0; ch < 8; ch++) {
                const float* cur = hs + (ch & 1) * BUFSZ;
                if (ch + 1 < 8) {
                    float* nxt = hs + ((ch + 1) & 1) * BUFSZ;
                    *(float4*)(nxt + srow * SH + sinner)     = a0;
                    *(float4*)(nxt + srow * SH + sinner + 4) = b0;
                }
                if (ch + 2 < 8)
                    ld_chunk(H1w, H, 8, H1w, H, ch + 2, rbase, srow, sinner, a0, b0);
                if (tid < 128) {
                    const float* hp = cur + vr * SH;
                    const float* wp = wmp + ch * 64;
#pragma unroll
                    for (int q = 0; q < 16; q++) {
                        float4 h4 = *(const float4*)(hp + (q << 2));
                        float4 w4 = __ldg((const float4*)(wp + (q << 2)));
                        acc4.x = fmaf(h4.x, w4.x, acc4.x);
                        acc4.y = fmaf(h4.y, w4.y, acc4.y);
                        acc4.z = fmaf(h4.z, w4.z, acc4.z);
                        acc4.w = fmaf(h4.w, w4.w, acc4.w);
                    }
                } else if (cj == 0 && tid < 224) {
                    const float* hp = cur + rl * SH;
                    const float* wp = wcp + ch * 64;
#pragma unroll
                    for (int q = 0; q < 16; q++) {
                        float4 h4 = *(const float4*)(hp + (q << 2));
                        float4 w4 = __ldg((const float4*)(wp + (q << 2)));
                        acc4.x = fmaf(h4.x, w4.x, acc4.x);
                        acc4.y = fmaf(h4.y, w4.y, acc4.y);
                        acc4.z = fmaf(h4.z, w4.z, acc4.z);
                        acc4.w = fmaf(h4.w, w4.w, acc4.w);
                    }
                }
                __syncthreads();
            }
            float acc = (acc4.x + acc4.y) + (acc4.z + acc4.w);
            if (cj == 0 && tid >= 128 && tid < 224)
                slg[t2] = acc + __ldg(bc + jj);
            __syncthreads();
            if (tid < 128) {
                int ccol = (cj << 2) + vc;
                int r = rbase + vr;
                float v   = acc + __ldg(bm + ccol) + g_Xp[r * 128 + NC + ccol];
                float nxt = val_seq[(size_t)(t + 1) * BATCH * NM + r * NM + ccol];
                g_Xp[r * 128 + NC + ccol] = (nxt != nxt) ? v : nxt;
            } else if (cj == 0 && tid < 224) {
                float l0 = slg[rl * 3 + 0], l1 = slg[rl * 3 + 1], l2 = slg[rl * 3 + 2];
                float m  = fmaxf(l0, fmaxf(l1, l2));
                float e0 = expf(l0 - m), e1 = expf(l1 - m), e2 = expf(l2 - m);
                float s  = e0 + e1 + e2;
                float oc = ((jj == 0) ? e0 : (jj == 1) ? e1 : e2) / s;
                int r = rbase + rl;
                out[(size_t)t * BATCH * NC + r * NC + jj] = oc;
                float nxt = cat_seq[(size_t)(t + 1) * BATCH * NC + r * NC + jj];
                g_Xp[r * 128 + jj] = (nxt != nxt) ? oc : nxt;
            }
        }
        // preload next step's phase-A chunks (H0w stable)
        if (t + 1 < T_STEPS) {
            ld_chunk(g_Xp, 128, SPLIT_A, H0w, H, START_A,     rbase, srow, sinner, pAa0, pAb0);
            ld_chunk(g_Xp, 128, SPLIT_A, H0w, H, START_A + 1, rbase, srow, sinner, pAa1, pAb1);
        }
        gridbar();
    }
}

// ---------------------------------------------------------------------------
extern "C" void kernel_launch(void* const* d_in, const int* in_sizes, int n_in,
                              void* d_out, int out_size)
{
    (void)in_sizes; (void)n_in; (void)out_size;
    cudaFuncSetAttribute(rnn_kernel,
                         cudaFuncAttributeMaxDynamicSharedMemorySize, SMEM_BYTES);
    rnn_kernel<<<GRIDN, NTHREADS, SMEM_BYTES>>>(
        (const float*)d_in[0],  (const float*)d_in[1],
        (const float*)d_in[2],  (const float*)d_in[3],  (const float*)d_in[4],
        (const float*)d_in[5],  (const float*)d_in[6],  (const float*)d_in[7],
        (const float*)d_in[8],  (const float*)d_in[9],
        (const float*)d_in[10], (const float*)d_in[11],
        (float*)d_out);
}